// round 4
// baseline (speedup 1.0000x reference)
#include <cuda_runtime.h>

typedef unsigned long long u64;

#define D      192
#define PLANE  (D*D)
#define OUTD   186
#define TX     16
#define TY     64
#define INY    70
#define SAW    24
#define T01W   18
#define T4W    20
#define ZCS    93
#define NSL    99          // 93 outputs + 6 halo slices per chunk
#define NT     256

// dynamic smem layout (bytes)
#define OFF_A    0          // raw X: [2][INY][SAW] f32 (buf stride 6720)
#define OFF_B    13440      // raw Y
#define RAW_BUF  6720
#define OFF_T01  26880      // [2][INY][T01W] u64 (buf stride 10080)
#define T01_BUF  10080
#define OFF_T23  47040
#define OFF_T4   67200      // [2][INY][T4W] f32 (buf stride 5600)
#define T4_BUF   5600
#define SMEM_TOTAL 78400

__device__ __forceinline__ u64 pack2(float lo, float hi){
    u64 r; asm("mov.b64 %0,{%1,%2};":"=l"(r):"f"(lo),"f"(hi)); return r;
}
__device__ __forceinline__ void unpack2(u64 v, float& lo, float& hi){
    asm("mov.b64 {%0,%1},%2;":"=f"(lo),"=f"(hi):"l"(v));
}
__device__ __forceinline__ u64 fma2(u64 a,u64 b,u64 c){
    u64 d; asm("fma.rn.f32x2 %0,%1,%2,%3;":"=l"(d):"l"(a),"l"(b),"l"(c)); return d;
}
__device__ __forceinline__ u64 mul2(u64 a,u64 b){
    u64 d; asm("mul.rn.f32x2 %0,%1,%2;":"=l"(d):"l"(a),"l"(b)); return d;
}

// separable Gaussian weights (size 7, sigma 1.5)
#define W0f 0.0366328f
#define W1f 0.1112808f
#define W2f 0.2167453f
#define W3f 0.2706821f
__device__ __forceinline__ float wz(int k){
    if (k < 0 || k > 6) return 0.f;
    return (k==0||k==6)?W0f:(k==1||k==5)?W1f:(k==2||k==4)?W2f:W3f;
}
// compile-time packed weight pair (lo=wz(a), hi=wz(b))
__device__ __forceinline__ u64 wpz(int a,int b){
    return ((u64)__float_as_uint(wz(b))<<32) | (u64)__float_as_uint(wz(a));
}

#define CP_ASYNC16(dst, src) asm volatile("cp.async.cg.shared.global [%0], [%1], 16;" :: "r"(dst), "l"(src))
#define CP_COMMIT() asm volatile("cp.async.commit_group;")
#define CP_WAIT0()  asm volatile("cp.async.wait_group 0;")

__device__ double g_ssim_acc;
__global__ void ssim_zero_kernel(){ g_ssim_acc = 0.0; }

// x-direction conv of one (row, 4-col) task for 5 fields
__device__ __forceinline__ void xconv_task(char* SM, int bit, int row, int xc0){
    const float* pa = (const float*)(SM + OFF_A + bit*RAW_BUF) + row*SAW + xc0;
    const float* pb = (const float*)(SM + OFF_B + bit*RAW_BUF) + row*SAW + xc0;
    float a[10], b[10];
    {
        float4 u = *(const float4*)pa;
        float4 v = *(const float4*)(pa+4);
        float2 w = *(const float2*)(pa+8);
        a[0]=u.x;a[1]=u.y;a[2]=u.z;a[3]=u.w;a[4]=v.x;a[5]=v.y;a[6]=v.z;a[7]=v.w;a[8]=w.x;a[9]=w.y;
    }
    {
        float4 u = *(const float4*)pb;
        float4 v = *(const float4*)(pb+4);
        float2 w = *(const float2*)(pb+8);
        b[0]=u.x;b[1]=u.y;b[2]=u.z;b[3]=u.w;b[4]=v.x;b[5]=v.y;b[6]=v.z;b[7]=v.w;b[8]=w.x;b[9]=w.y;
    }
    u64 a01[4], a23[4];
    float xy[10];
    #pragma unroll
    for (int m=0;m<10;m++){
        u64 pab = pack2(a[m], b[m]);
        u64 psq = mul2(pab, pab);
        xy[m] = a[m]*b[m];
        #pragma unroll
        for (int c=0;c<4;c++){
            int k = m-c;
            if (k == 0){ a01[c]=mul2(wpz(0,0),pab); a23[c]=mul2(wpz(0,0),psq); }
            else if (k > 0 && k <= 6){ a01[c]=fma2(wpz(k,k),pab,a01[c]); a23[c]=fma2(wpz(k,k),psq,a23[c]); }
        }
    }
    // xy field: pair adjacent output cols through shifted packed-xy values
    u64 o4x0, o4x1;
    #pragma unroll
    for (int m=0;m<9;m++){
        u64 px = pack2(xy[m], xy[m+1]);
        if (m == 0)      o4x0 = mul2(wpz(0,0), px);
        else if (m <= 6) o4x0 = fma2(wpz(m,m), px, o4x0);
        if (m == 2)      o4x1 = mul2(wpz(0,0), px);
        else if (m > 2)  o4x1 = fma2(wpz(m-2,m-2), px, o4x1);
    }
    u64*   T01 = (u64*)(SM + OFF_T01 + bit*T01_BUF) + row*T01W + xc0;
    u64*   T23 = (u64*)(SM + OFF_T23 + bit*T01_BUF) + row*T01W + xc0;
    float* T4  = (float*)(SM + OFF_T4 + bit*T4_BUF) + row*T4W + xc0;
    ulonglong2 s;
    s.x=a01[0]; s.y=a01[1]; *(ulonglong2*)T01     = s;
    s.x=a01[2]; s.y=a01[3]; *(ulonglong2*)(T01+2) = s;
    s.x=a23[0]; s.y=a23[1]; *(ulonglong2*)T23     = s;
    s.x=a23[2]; s.y=a23[3]; *(ulonglong2*)(T23+2) = s;
    float4 f;
    unpack2(o4x0, f.x, f.y);
    unpack2(o4x1, f.z, f.w);
    *(float4*)T4 = f;
}

__global__ __launch_bounds__(NT,1)
void ssim_main_kernel(const float* __restrict__ X, const float* __restrict__ Y){
    extern __shared__ char SM[];
    __shared__ float red[NT/32];

    const int t   = threadIdx.x;
    const int txi = t & 15;
    const int g   = t >> 4;

    const int gx0   = blockIdx.x * TX;
    const int gy0   = blockIdx.y * TY;
    const int batch = blockIdx.z >> 1;
    const int chunk = blockIdx.z & 1;

    const float* Xb = X + (size_t)batch*PLANE*D + (size_t)(chunk*ZCS)*PLANE;
    const float* Yb = Y + (size_t)batch*PLANE*D + (size_t)(chunk*ZCS)*PLANE;

    // ---- cp.async chunk assignments: 2 arrays x 70 rows x 6 chunks = 840 ----
    const float* gp[4]; unsigned sad[4]; bool okr[4];
    #pragma unroll
    for (int r=0;r<4;r++){
        int cid = t + 256*r;
        okr[r] = (cid < 840);
        int arr = (cid >= 420) ? 1 : 0;
        int c = cid - 420*arr;
        if (!okr[r]) c = 0;
        int row = c/6, ck = c - 6*row;
        int gy = min(gy0 + row, D-1);
        int gx = gx0 + 4*ck; if (gx + 3 >= D) gx = gx0;   // only fully-unused chunks clamp
        gp[r] = (arr ? Yb : Xb) + gy*D + gx;
        sad[r] = (unsigned)__cvta_generic_to_shared(
                    SM + (arr ? OFF_B : OFF_A) + row*(SAW*4) + ck*16);
    }

    // ---- x-conv tasks: 280 (70 rows x 4 col-chunks); extras on warp 7 ----
    const int  row1 = t >> 2,       xc1 = (t & 3) * 4;
    const bool has2 = (t >= 232);
    const int  tau2 = t + 24;
    const int  row2 = tau2 >> 2,    xc2 = (tau2 & 3) * 4;

    const bool okx = (gx0 + txi) < OUTD;
    bool vy[4];
    #pragma unroll
    for (int c=0;c<4;c++) vy[c] = okx && ((gy0 + 4*g + c) < OUTD);

    // per-thread z rings: 4 rows; xy packed per row-pair
    u64 R01[4][7], R23[4][7], R45[2][7];

    float acc = 0.f;
    const float c1 = 1e-4f, c2 = 9e-4f;

    // prologue: load slice 0 into buffer 0
    #pragma unroll
    for (int r=0;r<4;r++){ if (okr[r]) CP_ASYNC16(sad[r], gp[r]); }
    CP_COMMIT();
    #pragma unroll
    for (int r=0;r<4;r++) gp[r] += PLANE;

    for (int base = 0; base <= NSL; base += 7){
        #pragma unroll
        for (int ph = 0; ph < 7; ++ph){
            const int it = base + ph;
            if (it > NSL) break;
            const int bit = it & 1;

            CP_WAIT0();
            __syncthreads();

            if (it < NSL - 1){
                unsigned bo = (unsigned)(((it+1)&1) * RAW_BUF);
                #pragma unroll
                for (int r=0;r<4;r++){ if (okr[r]) CP_ASYNC16(sad[r]+bo, gp[r]); }
                CP_COMMIT();
                #pragma unroll
                for (int r=0;r<4;r++) gp[r] += PLANE;
            } else {
                CP_COMMIT();
            }

            // ---- x-direction conv of slice it ----
            if (it < NSL){
                xconv_task(SM, bit, row1, xc1);
                if (has2) xconv_task(SM, bit, row2, xc2);
            }

            // ---- y-conv (4 rows) + ring + z-conv + SSIM for slice it-1 ----
            if (it >= 1){
                const int bp = bit ^ 1;
                const u64*   T01 = (const u64*)(SM + OFF_T01 + bp*T01_BUF);
                const u64*   T23 = (const u64*)(SM + OFF_T23 + bp*T01_BUF);
                const float* T4  = (const float*)(SM + OFF_T4 + bp*T4_BUF);

                u64 o01[4], o23[4], p45_0, p45_1;
                #pragma unroll
                for (int j=0;j<10;j++){
                    const int ir = 4*g + j;
                    u64   f01 = T01[ir*T01W + txi];
                    u64   f23 = T23[ir*T01W + txi];
                    float f4  = T4 [ir*T4W  + txi];
                    u64   f44 = pack2(f4, f4);
                    #pragma unroll
                    for (int c=0;c<4;c++){
                        int k = j - c;
                        if (k == 0){ o01[c] = mul2(wpz(0,0), f01); o23[c] = mul2(wpz(0,0), f23); }
                        else if (k > 0 && k <= 6){
                            o01[c] = fma2(wpz(k,k), f01, o01[c]);
                            o23[c] = fma2(wpz(k,k), f23, o23[c]);
                        }
                    }
                    // xy: rows (0,1) packed, rows (2,3) packed; zero-padded weights exact
                    if (j == 0)      p45_0 = mul2(wpz(0,-1), f44);
                    else if (j <= 7) p45_0 = fma2(wpz(j,j-1), f44, p45_0);
                    if (j == 2)      p45_1 = mul2(wpz(0,-1), f44);
                    else if (j > 2)  p45_1 = fma2(wpz(j-2,j-3), f44, p45_1);
                }
                const int RIDX = (ph + 6) % 7;     // (it-1) % 7, compile-time
                #pragma unroll
                for (int c=0;c<4;c++){ R01[c][RIDX]=o01[c]; R23[c][RIDX]=o23[c]; }
                R45[0][RIDX]=p45_0; R45[1][RIDX]=p45_1;

                if (it >= 7){
                    u64 m45p0, m45p1;
                    {
                        u64 m0 = mul2(wpz(0,0), R45[0][ph%7]);
                        u64 m1 = mul2(wpz(0,0), R45[1][ph%7]);
                        #pragma unroll
                        for (int k=1;k<7;k++){
                            m0 = fma2(wpz(k,k), R45[0][(ph+k)%7], m0);
                            m1 = fma2(wpz(k,k), R45[1][(ph+k)%7], m1);
                        }
                        m45p0 = m0; m45p1 = m1;
                    }
                    float m4v[4];
                    unpack2(m45p0, m4v[0], m4v[1]);
                    unpack2(m45p1, m4v[2], m4v[3]);
                    #pragma unroll
                    for (int c=0;c<4;c++){
                        if (vy[c]){
                            u64 m01 = mul2(wpz(0,0), R01[c][ph%7]);
                            u64 m23 = mul2(wpz(0,0), R23[c][ph%7]);
                            #pragma unroll
                            for (int k=1;k<7;k++){
                                m01 = fma2(wpz(k,k), R01[c][(ph+k)%7], m01);
                                m23 = fma2(wpz(k,k), R23[c][(ph+k)%7], m23);
                            }
                            float mu1,mu2,ex2,ey2;
                            unpack2(m01, mu1, mu2);
                            unpack2(m23, ex2, ey2);
                            float m1s = mu1*mu1, m2s = mu2*mu2, mm = mu1*mu2;
                            float num = (2.f*mm + c1) * (2.f*(m4v[c] - mm) + c2);
                            float den = (m1s + m2s + c1) * ((ex2 - m1s) + (ey2 - m2s) + c2);
                            acc += __fdividef(num, den);
                        }
                    }
                }
            }
        }
    }

    // ---- reduction ----
    #pragma unroll
    for (int o = 16; o > 0; o >>= 1)
        acc += __shfl_xor_sync(0xffffffffu, acc, o);
    if ((t & 31) == 0) red[t >> 5] = acc;
    __syncthreads();
    if (t < 32){
        float v = (t < NT/32) ? red[t] : 0.f;
        #pragma unroll
        for (int o = 16; o > 0; o >>= 1)
            v += __shfl_xor_sync(0xffffffffu, v, o);
        if (t == 0) atomicAdd(&g_ssim_acc, (double)v);
    }
}

__global__ void ssim_finalize_kernel(float* __restrict__ out){
    out[0] = (float)(g_ssim_acc / 12869712.0);   // 2 * 186^3
}

extern "C" void kernel_launch(void* const* d_in, const int* in_sizes, int n_in,
                              void* d_out, int out_size){
    const float* x = (const float*)d_in[0];
    const float* y = (const float*)d_in[1];
    float* out = (float*)d_out;

    cudaFuncSetAttribute(ssim_main_kernel,
                         cudaFuncAttributeMaxDynamicSharedMemorySize, SMEM_TOTAL);

    ssim_zero_kernel<<<1, 1>>>();
    dim3 grid(12, 3, 4);   // 12*16=192 (x), 3*64=192 (y), 2 batches * 2 z-chunks
    ssim_main_kernel<<<grid, NT, SMEM_TOTAL>>>(x, y);
    ssim_finalize_kernel<<<1, 1>>>(out);
}

// round 5
// speedup vs baseline: 1.1326x; 1.1326x over previous
#include <cuda_runtime.h>

typedef unsigned long long u64;

#define D      192
#define PLANE  (D*D)
#define OUTD   186
#define TX     16
#define TY     32
#define INY    38          // TY + 6
#define SAW    24          // padded raw row width (floats)
#define TABW   17          // padded interleaved (t01,t23) row width (ulonglong2)
#define T4W    20          // padded t4 row width (floats)
#define ZCS    93          // 2 z-chunks of exactly 93 outputs
#define NSL    99          // 93 + 6 halo slices per chunk
#define NT     256

__device__ __forceinline__ u64 pack2(float lo, float hi){
    u64 r; asm("mov.b64 %0,{%1,%2};":"=l"(r):"f"(lo),"f"(hi)); return r;
}
__device__ __forceinline__ void unpack2(u64 v, float& lo, float& hi){
    asm("mov.b64 {%0,%1},%2;":"=f"(lo),"=f"(hi):"l"(v));
}
__device__ __forceinline__ u64 fma2(u64 a,u64 b,u64 c){
    u64 d; asm("fma.rn.f32x2 %0,%1,%2,%3;":"=l"(d):"l"(a),"l"(b),"l"(c)); return d;
}
__device__ __forceinline__ u64 mul2(u64 a,u64 b){
    u64 d; asm("mul.rn.f32x2 %0,%1,%2;":"=l"(d):"l"(a),"l"(b)); return d;
}

// separable Gaussian weights (size 7, sigma 1.5); wz(k)=0 outside [0,6]
#define W0f 0.0366328f
#define W1f 0.1112808f
#define W2f 0.2167453f
#define W3f 0.2706821f
__device__ __forceinline__ float wz(int k){
    if (k < 0 || k > 6) return 0.f;
    return (k==0||k==6)?W0f:(k==1||k==5)?W1f:(k==2||k==4)?W2f:W3f;
}
__device__ __forceinline__ u64 wpz(int a,int b){   // packed (lo=wz(a), hi=wz(b)); compile-time
    return ((u64)__float_as_uint(wz(b))<<32) | (u64)__float_as_uint(wz(a));
}

#define CP_ASYNC16(dst, src) asm volatile("cp.async.cg.shared.global [%0], [%1], 16;" :: "r"(dst), "l"(src))
#define CP_COMMIT() asm volatile("cp.async.commit_group;")
#define CP_WAIT1()  asm volatile("cp.async.wait_group 1;")

__device__ double g_ssim_acc;
__global__ void ssim_zero_kernel(){ g_ssim_acc = 0.0; }

// x-direction conv of one (row, 4-col) task for all 5 fields
__device__ __forceinline__ void xconv_task(
    const float (*sa_)[SAW], const float (*sb_)[SAW],
    ulonglong2 (*tab)[TABW], float (*t4_)[T4W],
    int row, int xc0)
{
    const float* pa = &sa_[row][xc0];
    const float* pb = &sb_[row][xc0];
    float a[10], b[10];
    {
        float4 u = *(const float4*)pa;
        float4 v = *(const float4*)(pa+4);
        float2 w = *(const float2*)(pa+8);
        a[0]=u.x;a[1]=u.y;a[2]=u.z;a[3]=u.w;a[4]=v.x;a[5]=v.y;a[6]=v.z;a[7]=v.w;a[8]=w.x;a[9]=w.y;
    }
    {
        float4 u = *(const float4*)pb;
        float4 v = *(const float4*)(pb+4);
        float2 w = *(const float2*)(pb+8);
        b[0]=u.x;b[1]=u.y;b[2]=u.z;b[3]=u.w;b[4]=v.x;b[5]=v.y;b[6]=v.z;b[7]=v.w;b[8]=w.x;b[9]=w.y;
    }
    u64 a01[4], a23[4];
    float xy[10];
    #pragma unroll
    for (int m=0;m<10;m++){
        u64 pab = pack2(a[m], b[m]);
        u64 psq = mul2(pab, pab);
        xy[m] = a[m]*b[m];
        #pragma unroll
        for (int c=0;c<4;c++){
            int k = m-c;
            if (k == 0){ a01[c]=mul2(wpz(0,0),pab); a23[c]=mul2(wpz(0,0),psq); }
            else if (k > 0 && k <= 6){ a01[c]=fma2(wpz(k,k),pab,a01[c]); a23[c]=fma2(wpz(k,k),psq,a23[c]); }
        }
    }
    // xy field: pair adjacent output cols via shifted packed values (exact)
    u64 o4x0, o4x1;
    #pragma unroll
    for (int m=0;m<9;m++){
        u64 px = pack2(xy[m], xy[m+1]);
        if (m == 0)      o4x0 = mul2(wpz(0,0), px);
        else if (m <= 6) o4x0 = fma2(wpz(m,m), px, o4x0);
        if (m == 2)      o4x1 = mul2(wpz(0,0), px);
        else if (m > 2)  o4x1 = fma2(wpz(m-2,m-2), px, o4x1);
    }
    #pragma unroll
    for (int c=0;c<4;c++){
        ulonglong2 s; s.x = a01[c]; s.y = a23[c];
        tab[row][xc0 + c] = s;
    }
    float4 f;
    unpack2(o4x0, f.x, f.y);
    unpack2(o4x1, f.z, f.w);
    *(float4*)&t4_[row][xc0] = f;
}

__global__ __launch_bounds__(NT,2)
void ssim_main_kernel(const float* __restrict__ X, const float* __restrict__ Y){
    __shared__ float      sa [3][INY][SAW];
    __shared__ float      sb [3][INY][SAW];
    __shared__ ulonglong2 tAB[2][INY][TABW];   // interleaved (t01, t23)
    __shared__ float      t4s[2][INY][T4W];
    __shared__ float      red[NT/32];

    const int t   = threadIdx.x;
    const int txi = t & 15;
    const int q   = t >> 4;

    const int gx0   = blockIdx.x * TX;
    const int gy0   = blockIdx.y * TY;
    const int batch = blockIdx.z >> 1;
    const int chunk = blockIdx.z & 1;

    const float* xb = X + (size_t)batch*PLANE*D + (size_t)(chunk*ZCS)*PLANE;
    const float* yb = Y + (size_t)batch*PLANE*D + (size_t)(chunk*ZCS)*PLANE;

    // ---- cp.async chunk assignment: 2 arrays x 38 rows x 6 chunks = 456 ----
    const float* p1; const float* p2;
    unsigned s1, s2; const bool have2 = (t < 200);
    {
        int cid1 = t;
        int c1   = (cid1 < 228) ? cid1 : cid1 - 228;
        int r1_  = c1/6, ck1 = c1 - 6*r1_;
        int gy1  = min(gy0 + r1_, D-1);
        int gxc1 = gx0 + ck1*4; if (gxc1 + 3 >= D) gxc1 = gx0;
        p1 = ((cid1 < 228) ? xb : yb) + gy1*D + gxc1;
        s1 = (unsigned)__cvta_generic_to_shared(
                 (cid1 < 228) ? (void*)&sa[0][r1_][ck1*4] : (void*)&sb[0][r1_][ck1*4]);
        int cid2 = t + 256;
        int c2   = cid2 - 228;               // always array b
        int r2_  = c2/6, ck2 = c2 - 6*r2_;
        int gy2  = min(gy0 + r2_, D-1);
        int gxc2 = gx0 + ck2*4; if (gxc2 + 3 >= D) gxc2 = gx0;
        p2 = yb + gy2*D + gxc2;
        s2 = (unsigned)__cvta_generic_to_shared(&sb[0][r2_][ck2*4]);
    }
    const unsigned BUFOFF = (unsigned)(INY * SAW * sizeof(float));   // 3648

    // x-conv: 152 tasks (38 rows x 4 col-chunks), threads 0..151
    const bool xact = (t < 152);
    const int  xrow = t >> 2;
    const int  xc0  = (t & 3) * 4;

    // per-thread z rings: 2 output rows; xy packed per row-pair
    u64 Ra01[7], Ra23[7], Rb01[7], Rb23[7], R45[7];

    const int  r0 = 2*q, r1 = 2*q + 1;
    const bool okx = (gx0 + txi) < OUTD;
    const bool v0  = okx && (gy0 + r0 < OUTD);
    const bool v1  = okx && (gy0 + r1 < OUTD);

    const float c1c = 1e-4f, c2c = 9e-4f;
    float acc = 0.f;

    // ---- prologue: slices 0 and 1 into buffers 0, 1 ----
    CP_ASYNC16(s1, p1); if (have2) CP_ASYNC16(s2, p2);
    CP_COMMIT();
    p1 += PLANE; p2 += PLANE;
    CP_ASYNC16(s1 + BUFOFF, p1); if (have2) CP_ASYNC16(s2 + BUFOFF, p2);
    CP_COMMIT();
    p1 += PLANE; p2 += PLANE;

    int bc = 0;   // raw buffer of slice it
    int bn = 2;   // raw buffer of slice it+2

    for (int base = 0; base <= NSL; base += 7){
        #pragma unroll
        for (int ph = 0; ph < 7; ++ph){
            const int it = base + ph;
            if (it > NSL) break;
            const int bit = it & 1;

            CP_WAIT1();          // slice it complete (it+1 may be in flight)
            __syncthreads();

            // issue slice it+2
            if (it + 2 < NSL){
                unsigned bo = (unsigned)bn * BUFOFF;
                CP_ASYNC16(s1 + bo, p1); if (have2) CP_ASYNC16(s2 + bo, p2);
                p1 += PLANE; p2 += PLANE;
            }
            CP_COMMIT();         // unconditional: keeps group accounting aligned

            // ---- x-direction conv of slice it ----
            if (it < NSL && xact)
                xconv_task(sa[bc], sb[bc], tAB[bit], t4s[bit], xrow, xc0);

            // ---- y-conv + ring + z-conv + SSIM for slice it-1 ----
            if (it >= 1){
                const int bp = bit ^ 1;
                u64 oa01, oa23, ob01, ob23, p45;
                #pragma unroll
                for (int j = 0; j < 8; ++j){
                    ulonglong2 f = tAB[bp][r0 + j][txi];
                    float f4 = t4s[bp][r0 + j][txi];
                    u64 f44 = pack2(f4, f4);
                    if (j == 0){
                        oa01 = mul2(wpz(0,0), f.x);
                        oa23 = mul2(wpz(0,0), f.y);
                        p45  = mul2(wpz(0,-1), f44);
                        ob01 = 0; ob23 = 0;
                    } else {
                        if (j < 7){
                            oa01 = fma2(wpz(j,j), f.x, oa01);
                            oa23 = fma2(wpz(j,j), f.y, oa23);
                        }
                        if (j == 1){
                            ob01 = mul2(wpz(0,0), f.x);
                            ob23 = mul2(wpz(0,0), f.y);
                        } else {
                            ob01 = fma2(wpz(j-1,j-1), f.x, ob01);
                            ob23 = fma2(wpz(j-1,j-1), f.y, ob23);
                        }
                        p45 = fma2(wpz(j,j-1), f44, p45);   // wz(7)=0 pads row0 at j=7
                    }
                }
                const int RIDX = (ph + 6) % 7;    // (it-1) % 7, compile-time
                Ra01[RIDX]=oa01; Ra23[RIDX]=oa23;
                Rb01[RIDX]=ob01; Rb23[RIDX]=ob23; R45[RIDX]=p45;

                if (it >= 7){
                    u64 m45 = mul2(wpz(0,0), R45[ph%7]);
                    #pragma unroll
                    for (int k=1;k<7;k++) m45 = fma2(wpz(k,k), R45[(ph+k)%7], m45);
                    float m4a, m4b; unpack2(m45, m4a, m4b);

                    if (v0){
                        u64 m01 = mul2(wpz(0,0), Ra01[ph%7]);
                        u64 m23 = mul2(wpz(0,0), Ra23[ph%7]);
                        #pragma unroll
                        for (int k=1;k<7;k++){
                            m01 = fma2(wpz(k,k), Ra01[(ph+k)%7], m01);
                            m23 = fma2(wpz(k,k), Ra23[(ph+k)%7], m23);
                        }
                        float mu1,mu2,ex2,ey2;
                        unpack2(m01, mu1, mu2);
                        unpack2(m23, ex2, ey2);
                        float m1s=mu1*mu1, m2s=mu2*mu2, mm=mu1*mu2;
                        float num = (2.f*mm + c1c) * (2.f*(m4a - mm) + c2c);
                        float den = (m1s + m2s + c1c) * ((ex2 - m1s) + (ey2 - m2s) + c2c);
                        acc += __fdividef(num, den);
                    }
                    if (v1){
                        u64 m01 = mul2(wpz(0,0), Rb01[ph%7]);
                        u64 m23 = mul2(wpz(0,0), Rb23[ph%7]);
                        #pragma unroll
                        for (int k=1;k<7;k++){
                            m01 = fma2(wpz(k,k), Rb01[(ph+k)%7], m01);
                            m23 = fma2(wpz(k,k), Rb23[(ph+k)%7], m23);
                        }
                        float mu1,mu2,ex2,ey2;
                        unpack2(m01, mu1, mu2);
                        unpack2(m23, ex2, ey2);
                        float m1s=mu1*mu1, m2s=mu2*mu2, mm=mu1*mu2;
                        float num = (2.f*mm + c1c) * (2.f*(m4b - mm) + c2c);
                        float den = (m1s + m2s + c1c) * ((ex2 - m1s) + (ey2 - m2s) + c2c);
                        acc += __fdividef(num, den);
                    }
                }
            }

            bc = (bc == 2) ? 0 : bc + 1;
            bn = (bn == 2) ? 0 : bn + 1;
        }
    }

    // ---- reduction ----
    #pragma unroll
    for (int o = 16; o > 0; o >>= 1)
        acc += __shfl_xor_sync(0xffffffffu, acc, o);
    if ((t & 31) == 0) red[t >> 5] = acc;
    __syncthreads();
    if (t < 32){
        float v = (t < NT/32) ? red[t] : 0.f;
        #pragma unroll
        for (int o = 16; o > 0; o >>= 1)
            v += __shfl_xor_sync(0xffffffffu, v, o);
        if (t == 0) atomicAdd(&g_ssim_acc, (double)v);
    }
}

__global__ void ssim_finalize_kernel(float* __restrict__ out){
    out[0] = (float)(g_ssim_acc / 12869712.0);   // 2 * 186^3
}

extern "C" void kernel_launch(void* const* d_in, const int* in_sizes, int n_in,
                              void* d_out, int out_size){
    const float* x = (const float*)d_in[0];
    const float* y = (const float*)d_in[1];
    float* out = (float*)d_out;

    ssim_zero_kernel<<<1, 1>>>();
    dim3 grid(12, 6, 4);   // 192/16 x-tiles, 192/32 y-tiles, 2 batches * 2 z-chunks
    ssim_main_kernel<<<grid, NT>>>(x, y);
    ssim_finalize_kernel<<<1, 1>>>(out);
}

// round 6
// speedup vs baseline: 1.1829x; 1.0444x over previous
#include <cuda_runtime.h>

typedef unsigned long long u64;

#define D      192
#define PLANE  (D*D)
#define OUTD   186
#define TX     16
#define TY     32
#define INY    38          // TY + 6
#define SAW    24          // padded raw row width (floats)
#define TABW   17          // padded (t01,t23) row width (ulonglong2)
#define T4W    20          // padded t4 row width (floats)
#define NT     256

// dynamic smem layout (bytes); 4 buffers of each kind
#define RAW_BUF  3648u      // 38*24*4
#define TAB_BUF  10336u     // 38*17*16
#define T4_BUF   3040u      // 38*20*4
#define OFF_A    0u
#define OFF_B    14592u     // 4*RAW_BUF
#define OFF_TAB  29184u
#define OFF_T4   70528u     // 29184 + 4*TAB_BUF
#define SMEM_TOTAL 82688    // 70528 + 4*T4_BUF

__device__ __forceinline__ u64 pack2(float lo, float hi){
    u64 r; asm("mov.b64 %0,{%1,%2};":"=l"(r):"f"(lo),"f"(hi)); return r;
}
__device__ __forceinline__ void unpack2(u64 v, float& lo, float& hi){
    asm("mov.b64 {%0,%1},%2;":"=f"(lo),"=f"(hi):"l"(v));
}
__device__ __forceinline__ u64 fma2(u64 a,u64 b,u64 c){
    u64 d; asm("fma.rn.f32x2 %0,%1,%2,%3;":"=l"(d):"l"(a),"l"(b),"l"(c)); return d;
}
__device__ __forceinline__ u64 mul2(u64 a,u64 b){
    u64 d; asm("mul.rn.f32x2 %0,%1,%2;":"=l"(d):"l"(a),"l"(b)); return d;
}

// separable Gaussian weights (size 7, sigma 1.5); wz(k)=0 outside [0,6]
#define W0f 0.0366328f
#define W1f 0.1112808f
#define W2f 0.2167453f
#define W3f 0.2706821f
__device__ __forceinline__ float wz(int k){
    if (k < 0 || k > 6) return 0.f;
    return (k==0||k==6)?W0f:(k==1||k==5)?W1f:(k==2||k==4)?W2f:W3f;
}
__device__ __forceinline__ u64 wpz(int a,int b){   // packed (lo=wz(a), hi=wz(b)); folds to constant
    return ((u64)__float_as_uint(wz(b))<<32) | (u64)__float_as_uint(wz(a));
}

#define CP_ASYNC16(dst, src) asm volatile("cp.async.cg.shared.global [%0], [%1], 16;" :: "r"(dst), "l"(src))
#define CP_COMMIT() asm volatile("cp.async.commit_group;")
#define CP_WAIT0()  asm volatile("cp.async.wait_group 0;")

__device__ double g_ssim_acc;
__global__ void ssim_zero_kernel(){ g_ssim_acc = 0.0; }

// x-direction conv of one (row, 4-col) task, all 5 fields
__device__ __forceinline__ void xconv_task(char* SM, unsigned rawOffA, unsigned rawOffB,
                                           unsigned tabOff, unsigned t4Off, int row, int xc0){
    const float* pa = (const float*)(SM + rawOffA) + row*SAW + xc0;
    const float* pb = (const float*)(SM + rawOffB) + row*SAW + xc0;
    float a[10], b[10];
    {
        float4 u = *(const float4*)pa;
        float4 v = *(const float4*)(pa+4);
        float2 w = *(const float2*)(pa+8);
        a[0]=u.x;a[1]=u.y;a[2]=u.z;a[3]=u.w;a[4]=v.x;a[5]=v.y;a[6]=v.z;a[7]=v.w;a[8]=w.x;a[9]=w.y;
    }
    {
        float4 u = *(const float4*)pb;
        float4 v = *(const float4*)(pb+4);
        float2 w = *(const float2*)(pb+8);
        b[0]=u.x;b[1]=u.y;b[2]=u.z;b[3]=u.w;b[4]=v.x;b[5]=v.y;b[6]=v.z;b[7]=v.w;b[8]=w.x;b[9]=w.y;
    }
    u64 a01[4], a23[4];
    float xy[10];
    #pragma unroll
    for (int m=0;m<10;m++){
        u64 pab = pack2(a[m], b[m]);
        u64 psq = mul2(pab, pab);
        xy[m] = a[m]*b[m];
        #pragma unroll
        for (int c=0;c<4;c++){
            int k = m-c;
            if (k == 0){ a01[c]=mul2(wpz(0,0),pab); a23[c]=mul2(wpz(0,0),psq); }
            else if (k > 0 && k <= 6){ a01[c]=fma2(wpz(k,k),pab,a01[c]); a23[c]=fma2(wpz(k,k),psq,a23[c]); }
        }
    }
    u64 o4x0, o4x1;
    #pragma unroll
    for (int m=0;m<9;m++){
        u64 px = pack2(xy[m], xy[m+1]);
        if (m == 0)      o4x0 = mul2(wpz(0,0), px);
        else if (m <= 6) o4x0 = fma2(wpz(m,m), px, o4x0);
        if (m == 2)      o4x1 = mul2(wpz(0,0), px);
        else if (m > 2)  o4x1 = fma2(wpz(m-2,m-2), px, o4x1);
    }
    ulonglong2* tab = (ulonglong2*)(SM + tabOff) + row*TABW + xc0;
    #pragma unroll
    for (int c=0;c<4;c++){
        ulonglong2 s; s.x = a01[c]; s.y = a23[c];
        tab[c] = s;
    }
    float4 f;
    unpack2(o4x0, f.x, f.y);
    unpack2(o4x1, f.z, f.w);
    *(float4*)((float*)(SM + t4Off) + row*T4W + xc0) = f;
}

// y-direction conv (2 adjacent output rows) from one x-conved slice buffer
__device__ __forceinline__ void ystage(const char* SM, unsigned tabOff, unsigned t4Off,
                                       int r0, int txi,
                                       u64& oa01, u64& oa23, u64& ob01, u64& ob23, u64& p45){
    const ulonglong2* tab = (const ulonglong2*)(SM + tabOff);
    const float*      t4  = (const float*)(SM + t4Off);
    #pragma unroll
    for (int j = 0; j < 8; ++j){
        ulonglong2 f = tab[(r0 + j)*TABW + txi];
        float f4 = t4[(r0 + j)*T4W + txi];
        u64 f44 = pack2(f4, f4);
        if (j == 0){
            oa01 = mul2(wpz(0,0), f.x);
            oa23 = mul2(wpz(0,0), f.y);
            p45  = mul2(wpz(0,-1), f44);
        } else {
            if (j < 7){
                oa01 = fma2(wpz(j,j), f.x, oa01);
                oa23 = fma2(wpz(j,j), f.y, oa23);
            }
            if (j == 1){
                ob01 = mul2(wpz(0,0), f.x);
                ob23 = mul2(wpz(0,0), f.y);
            } else {
                ob01 = fma2(wpz(j-1,j-1), f.x, ob01);
                ob23 = fma2(wpz(j-1,j-1), f.y, ob23);
            }
            p45 = fma2(wpz(j,j-1), f44, p45);   // wz(7)=0 pads row0 at j=7
        }
    }
}

// z-conv + SSIM for one sy; B = (sy+1)%7 (oldest ring entry); folds after unroll
__device__ __forceinline__ void zssim(const u64* Ra01, const u64* Ra23,
                                      const u64* Rb01, const u64* Rb23,
                                      const u64* R45, int B,
                                      bool v0, bool v1, float& acc){
    const float c1c = 1e-4f, c2c = 9e-4f;
    u64 m45 = mul2(wpz(0,0), R45[B % 7]);
    #pragma unroll
    for (int k = 1; k < 7; ++k) m45 = fma2(wpz(k,k), R45[(B + k) % 7], m45);
    float m4a, m4b; unpack2(m45, m4a, m4b);
    if (v0){
        u64 m01 = mul2(wpz(0,0), Ra01[B % 7]);
        u64 m23 = mul2(wpz(0,0), Ra23[B % 7]);
        #pragma unroll
        for (int k = 1; k < 7; ++k){
            m01 = fma2(wpz(k,k), Ra01[(B + k) % 7], m01);
            m23 = fma2(wpz(k,k), Ra23[(B + k) % 7], m23);
        }
        float mu1,mu2,ex2,ey2;
        unpack2(m01, mu1, mu2);
        unpack2(m23, ex2, ey2);
        float m1s=mu1*mu1, m2s=mu2*mu2, mm=mu1*mu2;
        float num = (2.f*mm + c1c) * (2.f*(m4a - mm) + c2c);
        float den = (m1s + m2s + c1c) * ((ex2 - m1s) + (ey2 - m2s) + c2c);
        acc += __fdividef(num, den);
    }
    if (v1){
        u64 m01 = mul2(wpz(0,0), Rb01[B % 7]);
        u64 m23 = mul2(wpz(0,0), Rb23[B % 7]);
        #pragma unroll
        for (int k = 1; k < 7; ++k){
            m01 = fma2(wpz(k,k), Rb01[(B + k) % 7], m01);
            m23 = fma2(wpz(k,k), Rb23[(B + k) % 7], m23);
        }
        float mu1,mu2,ex2,ey2;
        unpack2(m01, mu1, mu2);
        unpack2(m23, ex2, ey2);
        float m1s=mu1*mu1, m2s=mu2*mu2, mm=mu1*mu2;
        float num = (2.f*mm + c1c) * (2.f*(m4b - mm) + c2c);
        float den = (m1s + m2s + c1c) * ((ex2 - m1s) + (ey2 - m2s) + c2c);
        acc += __fdividef(num, den);
    }
}

__global__ __launch_bounds__(NT,2)
void ssim_main_kernel(const float* __restrict__ X, const float* __restrict__ Y){
    extern __shared__ char SM[];
    __shared__ float red[NT/32];

    const int t   = threadIdx.x;
    const int txi = t & 15;
    const int q   = t >> 4;

    const int gx0   = blockIdx.x * TX;
    const int gy0   = blockIdx.y * TY;
    const int batch = blockIdx.z >> 1;
    const int chunk = blockIdx.z & 1;

    const float* xb = X + (size_t)batch*PLANE*D + (size_t)(chunk*93)*PLANE;
    const float* yb = Y + (size_t)batch*PLANE*D + (size_t)(chunk*93)*PLANE;

    // ---- cp.async chunk assignment: 2 arrays x 38 rows x 6 chunks = 456 ----
    const float* p1; const float* p2;
    unsigned s1, s2; const bool have2 = (t < 200);
    {
        int cid1 = t;
        int c1   = (cid1 < 228) ? cid1 : cid1 - 228;
        int r1_  = c1/6, ck1 = c1 - 6*r1_;
        int gy1  = min(gy0 + r1_, D-1);
        int gxc1 = gx0 + ck1*4; if (gxc1 + 3 >= D) gxc1 = gx0;
        p1 = ((cid1 < 228) ? xb : yb) + gy1*D + gxc1;
        s1 = (unsigned)__cvta_generic_to_shared(
                 SM + ((cid1 < 228) ? OFF_A : OFF_B) + (unsigned)(r1_*(SAW*4) + ck1*16));
        int cid2 = t + 256;
        int c2   = cid2 - 228;                 // always array b
        int r2_  = c2/6, ck2 = c2 - 6*r2_;
        int gy2  = min(gy0 + r2_, D-1);
        int gxc2 = gx0 + ck2*4; if (gxc2 + 3 >= D) gxc2 = gx0;
        p2 = yb + gy2*D + gxc2;
        s2 = (unsigned)__cvta_generic_to_shared(
                 SM + OFF_B + (unsigned)(r2_*(SAW*4) + ck2*16));
    }

    // x-conv: 152 tasks (38 rows x 4 col-chunks), threads 0..151
    const bool xact = (t < 152);
    const int  xrow = t >> 2;
    const int  xc0  = (t & 3) * 4;

    // per-thread z rings (2 output rows; xy packed per row-pair)
    u64 Ra01[7], Ra23[7], Rb01[7], Rb23[7], R45[7];

    const int  r0 = 2*q;
    const bool okx = (gx0 + txi) < OUTD;
    const bool v0  = okx && (gy0 + r0 < OUTD);
    const bool v1  = okx && (gy0 + r0 + 1 < OUTD);

    float acc = 0.f;

    // ---- prologue: slices 0,1 into raw buffers 0,1 (one group) ----
    CP_ASYNC16(s1, p1); if (have2) CP_ASYNC16(s2, p2);
    CP_ASYNC16(s1 + RAW_BUF, p1 + PLANE); if (have2) CP_ASYNC16(s2 + RAW_BUF, p2 + PLANE);
    CP_COMMIT();
    p1 += 2*PLANE; p2 += 2*PLANE;

    unsigned rawRd = 0;    // byte off of raw buffer pair holding slices (2ip, 2ip+1)
    unsigned tabWr = 0;    // byte off of tab buffer pair for x-conv writes
    unsigned t4Wr  = 0;

    // pair-iterations ip = 0..50: x-conv slices (2ip,2ip+1), y/z slices (2ip-2,2ip-1)
    for (int pb = 0; pb <= 50; pb += 7){
        #pragma unroll
        for (int pp = 0; pp < 7; ++pp){
            const int ip = pb + pp;
            if (ip > 50) break;

            CP_WAIT0();
            __syncthreads();

            // prefetch slices 2ip+2, 2ip+3 into the opposite raw buffer pair
            {
                unsigned rawW = rawRd ^ (2u*RAW_BUF);
                if (ip <= 48){ CP_ASYNC16(s1 + rawW, p1); if (have2) CP_ASYNC16(s2 + rawW, p2); }
                if (ip <= 47){ CP_ASYNC16(s1 + rawW + RAW_BUF, p1 + PLANE);
                               if (have2) CP_ASYNC16(s2 + rawW + RAW_BUF, p2 + PLANE); }
                CP_COMMIT();
                p1 += 2*PLANE; p2 += 2*PLANE;
            }

            // ---- x-conv of slices 2ip, 2ip+1 ----
            if (xact){
                if (ip <= 49)
                    xconv_task(SM, OFF_A + rawRd, OFF_B + rawRd,
                               OFF_TAB + tabWr, OFF_T4 + t4Wr, xrow, xc0);
                if (ip <= 48)
                    xconv_task(SM, OFF_A + rawRd + RAW_BUF, OFF_B + rawRd + RAW_BUF,
                               OFF_TAB + tabWr + TAB_BUF, OFF_T4 + t4Wr + T4_BUF, xrow, xc0);
            }

            // ---- y/z/SSIM for sy0 = 2ip-2, sy1 = 2ip-1 ----
            if (ip >= 1){
                const unsigned tabRd = tabWr ^ (2u*TAB_BUF);
                const unsigned t4Rd  = t4Wr  ^ (2u*T4_BUF);
                const int I0 = (2*pp + 5) % 7;   // sy0 % 7
                const int I1 = (2*pp + 6) % 7;   // sy1 % 7
                const int B0 = (2*pp + 6) % 7;   // (sy0+1) % 7
                const int B1 = (2*pp)     % 7;   // (sy1+1) % 7

                // sy0
                {
                    u64 oa01, oa23, ob01, ob23, p45;
                    ystage(SM, OFF_TAB + tabRd, OFF_T4 + t4Rd, r0, txi,
                           oa01, oa23, ob01, ob23, p45);
                    Ra01[I0]=oa01; Ra23[I0]=oa23; Rb01[I0]=ob01; Rb23[I0]=ob23; R45[I0]=p45;
                    if (ip >= 4)
                        zssim(Ra01, Ra23, Rb01, Rb23, R45, B0, v0, v1, acc);
                }
                // sy1 (must come after zssim(sy0): slot I1 still holds sy0-6 until here)
                if (ip <= 49){
                    u64 oa01, oa23, ob01, ob23, p45;
                    ystage(SM, OFF_TAB + tabRd + TAB_BUF, OFF_T4 + t4Rd + T4_BUF, r0, txi,
                           oa01, oa23, ob01, ob23, p45);
                    Ra01[I1]=oa01; Ra23[I1]=oa23; Rb01[I1]=ob01; Rb23[I1]=ob23; R45[I1]=p45;
                    if (ip >= 4)
                        zssim(Ra01, Ra23, Rb01, Rb23, R45, B1, v0, v1, acc);
                }
            }

            rawRd ^= 2u*RAW_BUF;
            tabWr ^= 2u*TAB_BUF;
            t4Wr  ^= 2u*T4_BUF;
        }
    }

    // ---- reduction ----
    #pragma unroll
    for (int o = 16; o > 0; o >>= 1)
        acc += __shfl_xor_sync(0xffffffffu, acc, o);
    if ((t & 31) == 0) red[t >> 5] = acc;
    __syncthreads();
    if (t < 32){
        float v = (t < NT/32) ? red[t] : 0.f;
        #pragma unroll
        for (int o = 16; o > 0; o >>= 1)
            v += __shfl_xor_sync(0xffffffffu, v, o);
        if (t == 0) atomicAdd(&g_ssim_acc, (double)v);
    }
}

__global__ void ssim_finalize_kernel(float* __restrict__ out){
    out[0] = (float)(g_ssim_acc / 12869712.0);   // 2 * 186^3
}

extern "C" void kernel_launch(void* const* d_in, const int* in_sizes, int n_in,
                              void* d_out, int out_size){
    const float* x = (const float*)d_in[0];
    const float* y = (const float*)d_in[1];
    float* out = (float*)d_out;

    cudaFuncSetAttribute(ssim_main_kernel,
                         cudaFuncAttributeMaxDynamicSharedMemorySize, SMEM_TOTAL);

    ssim_zero_kernel<<<1, 1>>>();
    dim3 grid(12, 6, 4);   // 192/16 x-tiles, 192/32 y-tiles, 2 batches * 2 z-chunks
    ssim_main_kernel<<<grid, NT, SMEM_TOTAL>>>(x, y);
    ssim_finalize_kernel<<<1, 1>>>(out);
}

// round 7
// speedup vs baseline: 1.5144x; 1.2803x over previous
#include <cuda_runtime.h>

typedef unsigned long long u64;

#define D      192
#define PLANE  (D*D)
#define OUTD   186
#define TX     16
#define TY     32
#define INY    38          // TY + 6
#define SAW    24          // padded raw row width (floats)
#define TABW   17          // padded (t01,tsp) row width (ulonglong2)
#define NT     256

// dynamic smem layout (bytes); 4 buffers of each kind
#define RAW_BUF  3648u      // 38*24*4
#define TAB_BUF  10336u     // 38*17*16
#define OFF_A    0u
#define OFF_B    14592u     // 4*RAW_BUF
#define OFF_TAB  29184u
#define SMEM_TOTAL 70528    // 29184 + 4*TAB_BUF

__device__ __forceinline__ u64 pack2(float lo, float hi){
    u64 r; asm("mov.b64 %0,{%1,%2};":"=l"(r):"f"(lo),"f"(hi)); return r;
}
__device__ __forceinline__ void unpack2(u64 v, float& lo, float& hi){
    asm("mov.b64 {%0,%1},%2;":"=f"(lo),"=f"(hi):"l"(v));
}
__device__ __forceinline__ u64 fma2(u64 a,u64 b,u64 c){
    u64 d; asm("fma.rn.f32x2 %0,%1,%2,%3;":"=l"(d):"l"(a),"l"(b),"l"(c)); return d;
}
__device__ __forceinline__ u64 mul2(u64 a,u64 b){
    u64 d; asm("mul.rn.f32x2 %0,%1,%2;":"=l"(d):"l"(a),"l"(b)); return d;
}

// separable Gaussian weights (size 7, sigma 1.5); wz(k)=0 outside [0,6]
#define W0f 0.0366328f
#define W1f 0.1112808f
#define W2f 0.2167453f
#define W3f 0.2706821f
__device__ __forceinline__ float wz(int k){
    if (k < 0 || k > 6) return 0.f;
    return (k==0||k==6)?W0f:(k==1||k==5)?W1f:(k==2||k==4)?W2f:W3f;
}
__device__ __forceinline__ u64 wpz(int a,int b){   // packed (lo=wz(a), hi=wz(b)); folds to constant
    return ((u64)__float_as_uint(wz(b))<<32) | (u64)__float_as_uint(wz(a));
}

#define CP_ASYNC16(dst, src) asm volatile("cp.async.cg.shared.global [%0], [%1], 16;" :: "r"(dst), "l"(src))
#define CP_COMMIT() asm volatile("cp.async.commit_group;")
#define CP_WAIT0()  asm volatile("cp.async.wait_group 0;")

__device__ double g_ssim_acc;
__global__ void ssim_zero_kernel(){ g_ssim_acc = 0.0; }

// x-direction conv of one (row, 4-col) task. Two packed fields:
//   t01 = conv_x(x, y)          tsp = conv_x(x^2 + y^2,  x*y)
__device__ __forceinline__ void xconv_task(char* SM, unsigned rawOffA, unsigned rawOffB,
                                           unsigned tabOff, int row, int xc0){
    const float* pa = (const float*)(SM + rawOffA) + row*SAW + xc0;
    const float* pb = (const float*)(SM + rawOffB) + row*SAW + xc0;
    float a[10], b[10];
    {
        float4 u = *(const float4*)pa;
        float4 v = *(const float4*)(pa+4);
        float2 w = *(const float2*)(pa+8);
        a[0]=u.x;a[1]=u.y;a[2]=u.z;a[3]=u.w;a[4]=v.x;a[5]=v.y;a[6]=v.z;a[7]=v.w;a[8]=w.x;a[9]=w.y;
    }
    {
        float4 u = *(const float4*)pb;
        float4 v = *(const float4*)(pb+4);
        float2 w = *(const float2*)(pb+8);
        b[0]=u.x;b[1]=u.y;b[2]=u.z;b[3]=u.w;b[4]=v.x;b[5]=v.y;b[6]=v.z;b[7]=v.w;b[8]=w.x;b[9]=w.y;
    }
    u64 a01[4], asp[4];
    #pragma unroll
    for (int m=0;m<10;m++){
        u64 pab = pack2(a[m], b[m]);
        float s = fmaf(b[m], b[m], a[m]*a[m]);
        float p = a[m]*b[m];
        u64 psp = pack2(s, p);
        #pragma unroll
        for (int c=0;c<4;c++){
            int k = m-c;
            if (k == 0){ a01[c]=mul2(wpz(0,0),pab); asp[c]=mul2(wpz(0,0),psp); }
            else if (k > 0 && k <= 6){ a01[c]=fma2(wpz(k,k),pab,a01[c]); asp[c]=fma2(wpz(k,k),psp,asp[c]); }
        }
    }
    ulonglong2* tab = (ulonglong2*)(SM + tabOff) + row*TABW + xc0;
    #pragma unroll
    for (int c=0;c<4;c++){
        ulonglong2 s; s.x = a01[c]; s.y = asp[c];
        tab[c] = s;
    }
}

// y-direction conv, 2 adjacent output rows, from one x-conved slice buffer
__device__ __forceinline__ void ystage(const char* SM, unsigned tabOff,
                                       int r0, int txi,
                                       u64& oa01, u64& oasp, u64& ob01, u64& obsp){
    const ulonglong2* tab = (const ulonglong2*)(SM + tabOff);
    #pragma unroll
    for (int j = 0; j < 8; ++j){
        ulonglong2 f = tab[(r0 + j)*TABW + txi];
        if (j == 0){
            oa01 = mul2(wpz(0,0), f.x);
            oasp = mul2(wpz(0,0), f.y);
        } else {
            if (j < 7){
                oa01 = fma2(wpz(j,j), f.x, oa01);
                oasp = fma2(wpz(j,j), f.y, oasp);
            }
            if (j == 1){
                ob01 = mul2(wpz(0,0), f.x);
                obsp = mul2(wpz(0,0), f.y);
            } else {
                ob01 = fma2(wpz(j-1,j-1), f.x, ob01);
                obsp = fma2(wpz(j-1,j-1), f.y, obsp);
            }
        }
    }
}

// z-conv + SSIM for one output row; B = (sy+1)%7 (oldest ring slot); folds after unroll
__device__ __forceinline__ void zssim_row(const u64* R01, const u64* Rsp, int B,
                                          bool v, float& acc){
    const float c1c = 1e-4f, c2c = 9e-4f;
    u64 m01 = mul2(wpz(0,0), R01[B % 7]);
    u64 msp = mul2(wpz(0,0), Rsp[B % 7]);
    #pragma unroll
    for (int k = 1; k < 7; ++k){
        m01 = fma2(wpz(k,k), R01[(B + k) % 7], m01);
        msp = fma2(wpz(k,k), Rsp[(B + k) % 7], msp);
    }
    float mu1,mu2,S,P;
    unpack2(m01, mu1, mu2);
    unpack2(msp, S, P);
    float m1s=mu1*mu1, m2s=mu2*mu2, mm=mu1*mu2;
    float num = (2.f*mm + c1c) * (2.f*(P - mm) + c2c);
    float den = (m1s + m2s + c1c) * ((S - m1s - m2s) + c2c);
    if (v) acc += __fdividef(num, den);
}

__global__ __launch_bounds__(NT,2)
void ssim_main_kernel(const float* __restrict__ X, const float* __restrict__ Y){
    extern __shared__ char SM[];
    __shared__ float red[NT/32];

    const int t   = threadIdx.x;
    const int txi = t & 15;
    const int q   = t >> 4;

    const int gx0   = blockIdx.x * TX;
    const int gy0   = blockIdx.y * TY;
    const int batch = blockIdx.z >> 1;
    const int chunk = blockIdx.z & 1;

    const float* xb = X + (size_t)batch*PLANE*D + (size_t)(chunk*93)*PLANE;
    const float* yb = Y + (size_t)batch*PLANE*D + (size_t)(chunk*93)*PLANE;

    // ---- cp.async chunk assignment: 2 arrays x 38 rows x 6 chunks = 456 ----
    const float* p1; const float* p2;
    unsigned s1, s2; const bool have2 = (t < 200);
    {
        int cid1 = t;
        int c1   = (cid1 < 228) ? cid1 : cid1 - 228;
        int r1_  = c1/6, ck1 = c1 - 6*r1_;
        int gy1  = min(gy0 + r1_, D-1);
        int gxc1 = gx0 + ck1*4; if (gxc1 + 3 >= D) gxc1 = gx0;
        p1 = ((cid1 < 228) ? xb : yb) + gy1*D + gxc1;
        s1 = (unsigned)__cvta_generic_to_shared(
                 SM + ((cid1 < 228) ? OFF_A : OFF_B) + (unsigned)(r1_*(SAW*4) + ck1*16));
        int cid2 = t + 256;
        int c2   = cid2 - 228;                 // always array b
        int r2_  = c2/6, ck2 = c2 - 6*r2_;
        int gy2  = min(gy0 + r2_, D-1);
        int gxc2 = gx0 + ck2*4; if (gxc2 + 3 >= D) gxc2 = gx0;
        p2 = yb + gy2*D + gxc2;
        s2 = (unsigned)__cvta_generic_to_shared(
                 SM + OFF_B + (unsigned)(r2_*(SAW*4) + ck2*16));
    }

    // x-conv: 152 tasks (38 rows x 4 col-chunks), threads 0..151
    const bool xact = (t < 152);
    const int  xrow = t >> 2;
    const int  xc0  = (t & 3) * 4;

    // per-thread z rings (2 output rows x 2 packed fields)
    u64 Ra01[7], Rasp[7], Rb01[7], Rbsp[7];

    const int  r0 = 2*q;
    const bool okx = (gx0 + txi) < OUTD;
    const bool v0  = okx && (gy0 + r0 < OUTD);
    const bool v1  = okx && (gy0 + r0 + 1 < OUTD);

    float acc = 0.f;

    // ---- prologue: slices 0,1 into raw buffers 0,1 (one group) ----
    CP_ASYNC16(s1, p1); if (have2) CP_ASYNC16(s2, p2);
    CP_ASYNC16(s1 + RAW_BUF, p1 + PLANE); if (have2) CP_ASYNC16(s2 + RAW_BUF, p2 + PLANE);
    CP_COMMIT();
    p1 += 2*PLANE; p2 += 2*PLANE;

    unsigned rawRd = 0;    // byte off of raw buffer pair holding slices (2ip, 2ip+1)
    unsigned tabWr = 0;    // byte off of tab buffer pair for x-conv writes

    // pair-iterations ip = 0..50: x-conv slices (2ip,2ip+1), y/z slices (2ip-2,2ip-1)
    for (int pb = 0; pb <= 50; pb += 7){
        #pragma unroll
        for (int pp = 0; pp < 7; ++pp){
            const int ip = pb + pp;
            if (ip > 50) break;

            CP_WAIT0();
            __syncthreads();

            // prefetch slices 2ip+2, 2ip+3 into the opposite raw buffer pair
            {
                unsigned rawW = rawRd ^ (2u*RAW_BUF);
                if (ip <= 48){ CP_ASYNC16(s1 + rawW, p1); if (have2) CP_ASYNC16(s2 + rawW, p2); }
                if (ip <= 47){ CP_ASYNC16(s1 + rawW + RAW_BUF, p1 + PLANE);
                               if (have2) CP_ASYNC16(s2 + rawW + RAW_BUF, p2 + PLANE); }
                CP_COMMIT();
                p1 += 2*PLANE; p2 += 2*PLANE;
            }

            // ---- x-conv of slices 2ip, 2ip+1 ----
            if (xact){
                if (ip <= 49)
                    xconv_task(SM, OFF_A + rawRd, OFF_B + rawRd,
                               OFF_TAB + tabWr, xrow, xc0);
                if (ip <= 48)
                    xconv_task(SM, OFF_A + rawRd + RAW_BUF, OFF_B + rawRd + RAW_BUF,
                               OFF_TAB + tabWr + TAB_BUF, xrow, xc0);
            }

            // ---- y/z/SSIM for sy0 = 2ip-2, sy1 = 2ip-1 ----
            if (ip >= 1){
                const unsigned tabRd = tabWr ^ (2u*TAB_BUF);
                const int I0 = (2*pp + 5) % 7;   // sy0 % 7
                const int I1 = (2*pp + 6) % 7;   // sy1 % 7
                const int B0 = (2*pp + 6) % 7;   // (sy0+1) % 7
                const int B1 = (2*pp)     % 7;   // (sy1+1) % 7

                // sy0
                {
                    u64 oa01, oasp, ob01, obsp;
                    ystage(SM, OFF_TAB + tabRd, r0, txi, oa01, oasp, ob01, obsp);
                    Ra01[I0]=oa01; Rasp[I0]=oasp; Rb01[I0]=ob01; Rbsp[I0]=obsp;
                    if (ip >= 4){
                        zssim_row(Ra01, Rasp, B0, v0, acc);
                        zssim_row(Rb01, Rbsp, B0, v1, acc);
                    }
                }
                // sy1 (after zssim(sy0): slot I1 still holds sy0-6 until here)
                if (ip <= 49){
                    u64 oa01, oasp, ob01, obsp;
                    ystage(SM, OFF_TAB + tabRd + TAB_BUF, r0, txi, oa01, oasp, ob01, obsp);
                    Ra01[I1]=oa01; Rasp[I1]=oasp; Rb01[I1]=ob01; Rbsp[I1]=obsp;
                    if (ip >= 4){
                        zssim_row(Ra01, Rasp, B1, v0, acc);
                        zssim_row(Rb01, Rbsp, B1, v1, acc);
                    }
                }
            }

            rawRd ^= 2u*RAW_BUF;
            tabWr ^= 2u*TAB_BUF;
        }
    }

    // ---- reduction ----
    #pragma unroll
    for (int o = 16; o > 0; o >>= 1)
        acc += __shfl_xor_sync(0xffffffffu, acc, o);
    if ((t & 31) == 0) red[t >> 5] = acc;
    __syncthreads();
    if (t < 32){
        float v = (t < NT/32) ? red[t] : 0.f;
        #pragma unroll
        for (int o = 16; o > 0; o >>= 1)
            v += __shfl_xor_sync(0xffffffffu, v, o);
        if (t == 0) atomicAdd(&g_ssim_acc, (double)v);
    }
}

__global__ void ssim_finalize_kernel(float* __restrict__ out){
    out[0] = (float)(g_ssim_acc / 12869712.0);   // 2 * 186^3
}

extern "C" void kernel_launch(void* const* d_in, const int* in_sizes, int n_in,
                              void* d_out, int out_size){
    const float* x = (const float*)d_in[0];
    const float* y = (const float*)d_in[1];
    float* out = (float*)d_out;

    cudaFuncSetAttribute(ssim_main_kernel,
                         cudaFuncAttributeMaxDynamicSharedMemorySize, SMEM_TOTAL);

    ssim_zero_kernel<<<1, 1>>>();
    dim3 grid(12, 6, 4);   // 192/16 x-tiles, 192/32 y-tiles, 2 batches * 2 z-chunks
    ssim_main_kernel<<<grid, NT, SMEM_TOTAL>>>(x, y);
    ssim_finalize_kernel<<<1, 1>>>(out);
}